// round 12
// baseline (speedup 1.0000x reference)
#include <cuda_runtime.h>
#include <cuda_fp16.h>
#include <cstdint>
#include <cstddef>

// Problem constants (fixed by the reference)
#define NSRC0 200000
#define NDST0 50000
#define NDST1 10000
#define E0    800000
#define E1    160000
#define D     128

#define AS  132  // fp32 stage row stride (floats)
#define ASH 136  // fp16 tile row stride (halves); 272 B/row == 16 B mod 128 -> ldmatrix conflict-free

#define NB0 49  // ceil(50000/1024)
#define NB1 10  // ceil(10000/1024)

// ---------------- device scratch (static globals; no allocation) ----------------
__device__ float g_h1[(size_t)NDST0 * D];    // layer-1 fp32 ADDC partial
__device__ float g_agg0[(size_t)NDST0 * D];
__device__ float g_agg1[(size_t)NDST1 * D];
__device__ __half g_h0h[(size_t)NSRC0 * D];  // h0 lives ONLY in fp16
__device__ __half g_h1h[(size_t)NDST0 * D];  // h1 lives ONLY in fp16

__device__ int g_cnt0[NDST0];
__device__ int g_off0[NDST0 + 1];
__device__ int g_cur0[NDST0];
__device__ int g_esrc0[E0];

__device__ int g_cnt1[NDST1];
__device__ int g_off1[NDST1 + 1];
__device__ int g_cur1[NDST1];
__device__ int g_esrc1[E1];

__device__ int g_bsum[NB0 + NB1];

// ---------------- helpers ----------------
__device__ __forceinline__ uint32_t smem_u32(const void* p) {
    uint32_t a;
    asm("{ .reg .u64 t; cvta.to.shared.u64 t, %1; cvt.u32.u64 %0, t; }" : "=r"(a) : "l"(p));
    return a;
}
#define CP_ASYNC16(dst, src) \
    asm volatile("cp.async.cg.shared.global [%0], [%1], 16;" :: "r"(dst), "l"(src) : "memory")
#define CP_COMMIT() asm volatile("cp.async.commit_group;" ::: "memory")
#define CP_WAIT0()  asm volatile("cp.async.wait_group 0;" ::: "memory")

#define LDSM4(r, addr) \
    asm volatile("ldmatrix.sync.aligned.m8n8.x4.shared.b16 {%0,%1,%2,%3}, [%4];" \
                 : "=r"((r)[0]), "=r"((r)[1]), "=r"((r)[2]), "=r"((r)[3]) : "r"(addr))

// m16n8k16 fp16 MMA, fp32 accumulate (same 10-bit mantissa as tf32 -> identical numerics)
__device__ __forceinline__ void mma_f16(float d[4], const uint32_t a[4], uint32_t b0, uint32_t b1) {
    asm volatile(
        "mma.sync.aligned.m16n8k16.row.col.f32.f16.f16.f32 "
        "{%0,%1,%2,%3}, {%4,%5,%6,%7}, {%8,%9}, {%0,%1,%2,%3};"
        : "+f"(d[0]), "+f"(d[1]), "+f"(d[2]), "+f"(d[3])
        : "r"(a[0]), "r"(a[1]), "r"(a[2]), "r"(a[3]), "r"(b0), "r"(b1));
}

// ---------------- CSR build ----------------
__global__ void zero_counts_kernel() {
    int i = blockIdx.x * blockDim.x + threadIdx.x;
    if (i < NDST0) g_cnt0[i] = 0;
    if (i < NDST1) g_cnt1[i] = 0;
}
__global__ void hist_kernel(const int* __restrict__ dst0, const int* __restrict__ dst1) {
    int i = blockIdx.x * blockDim.x + threadIdx.x;
    if (i < E0) atomicAdd(&g_cnt0[dst0[i]], 1);
    if (i < E1) atomicAdd(&g_cnt1[dst1[i]], 1);
}

__global__ void scan_blocks_kernel() {
    __shared__ int sums[1024];
    const int b = blockIdx.x;
    const int tid = threadIdx.x;
    const int graph = (b < NB0) ? 0 : 1;
    const int blk = graph ? (b - NB0) : b;
    const int n = graph ? NDST1 : NDST0;
    const int* cnt = graph ? g_cnt1 : g_cnt0;
    int* off = graph ? g_off1 : g_off0;

    const int i = blk * 1024 + tid;
    const int v = (i < n) ? cnt[i] : 0;
    sums[tid] = v;
    __syncthreads();
    #pragma unroll
    for (int d = 1; d < 1024; d <<= 1) {
        int x = (tid >= d) ? sums[tid - d] : 0;
        __syncthreads();
        sums[tid] += x;
        __syncthreads();
    }
    if (i < n) off[i] = sums[tid] - v;
    if (tid == 1023) g_bsum[b] = sums[1023];
}

__global__ void scan_apply_kernel() {
    __shared__ int s_base;
    const int b = blockIdx.x;
    const int tid = threadIdx.x;
    const int graph = (b < NB0) ? 0 : 1;
    const int blk = graph ? (b - NB0) : b;
    const int n = graph ? NDST1 : NDST0;
    int* off = graph ? g_off1 : g_off0;
    int* cur = graph ? g_cur1 : g_cur0;
    if (tid == 0) {
        int base = 0;
        int start = graph ? NB0 : 0;
        for (int j = start; j < b; j++) base += g_bsum[j];
        s_base = base;
        if (b == 0) g_off0[NDST0] = E0;
        if (b == NB0) g_off1[NDST1] = E1;
    }
    __syncthreads();
    const int base = s_base;
    const int i = blk * 1024 + tid;
    if (i < n) {
        int o = off[i] + base;
        off[i] = o;
        cur[i] = o;
    }
}

__global__ void scatter_kernel(const int* __restrict__ src0, const int* __restrict__ dst0,
                               const int* __restrict__ src1, const int* __restrict__ dst1) {
    int i = blockIdx.x * blockDim.x + threadIdx.x;
    if (i < E0) { int pos = atomicAdd(&g_cur0[dst0[i]], 1); g_esrc0[pos] = src0[i]; }
    if (i < E1) { int pos = atomicAdd(&g_cur1[dst1[i]], 1); g_esrc1[pos] = src1[i]; }
}

// ---------------- mean aggregation over fp16 messages, fp32 accumulate ----------------
__global__ void aggregate_kernel(const __half* __restrict__ hh,
                                 const int* __restrict__ off,
                                 const int* __restrict__ esrc, float* __restrict__ agg,
                                 int ndst) {
    int gw = (blockIdx.x * blockDim.x + threadIdx.x) >> 5;
    int lane = threadIdx.x & 31;
    if (gw >= ndst) return;
    int s = off[gw], e = off[gw + 1];
    float4 acc = make_float4(0.f, 0.f, 0.f, 0.f);
    float4 acc2 = make_float4(0.f, 0.f, 0.f, 0.f);
    int i = s;
    for (; i + 2 <= e; i += 2) {
        const uint2* r0 = reinterpret_cast<const uint2*>(hh + (size_t)esrc[i] * D);
        const uint2* r1 = reinterpret_cast<const uint2*>(hh + (size_t)esrc[i + 1] * D);
        uint2 u0 = __ldg(&r0[lane]);
        uint2 u1 = __ldg(&r1[lane]);
        float2 p0 = __half22float2(*reinterpret_cast<__half2*>(&u0.x));
        float2 p1 = __half22float2(*reinterpret_cast<__half2*>(&u0.y));
        float2 q0 = __half22float2(*reinterpret_cast<__half2*>(&u1.x));
        float2 q1 = __half22float2(*reinterpret_cast<__half2*>(&u1.y));
        acc.x += p0.x;  acc.y += p0.y;  acc.z += p1.x;  acc.w += p1.y;
        acc2.x += q0.x; acc2.y += q0.y; acc2.z += q1.x; acc2.w += q1.y;
    }
    if (i < e) {
        const uint2* r0 = reinterpret_cast<const uint2*>(hh + (size_t)esrc[i] * D);
        uint2 u0 = __ldg(&r0[lane]);
        float2 p0 = __half22float2(*reinterpret_cast<__half2*>(&u0.x));
        float2 p1 = __half22float2(*reinterpret_cast<__half2*>(&u0.y));
        acc.x += p0.x; acc.y += p0.y; acc.z += p1.x; acc.w += p1.y;
    }
    acc.x += acc2.x; acc.y += acc2.y; acc.z += acc2.z; acc.w += acc2.w;
    float inv = 1.0f / fmaxf((float)(e - s), 1.0f);
    acc.x *= inv; acc.y *= inv; acc.z *= inv; acc.w *= inv;
    reinterpret_cast<float4*>(agg + (size_t)gw * D)[lane] = acc;
}

// ---------------- fp16 HMMA GEMM (m16n8k16, fp32 accum, ldmatrix frags) ----------------
__device__ __forceinline__ void cp_a_tile(float* Sg, const float* __restrict__ A,
                                          int m0, int M, int t) {
    uint32_t sb = smem_u32(Sg);
    #pragma unroll
    for (int j = 0; j < 16; j++) {
        int lin = t + 256 * j;
        int row = lin >> 5;
        int c4  = lin & 31;
        int gm  = m0 + row;
        if (gm < M)
            CP_ASYNC16(sb + (uint32_t)(row * AS + c4 * 4) * 4,
                       A + (size_t)gm * D + c4 * 4);
    }
}

__device__ __forceinline__ void convert_stage(const float* Sg, __half* Af, int t) {
    #pragma unroll
    for (int j = 0; j < 8; j++) {
        int lin = t + 256 * j;
        int row = lin >> 4;
        int c8  = lin & 15;
        float4 v0 = *reinterpret_cast<const float4*>(Sg + row * AS + c8 * 8);
        float4 v1 = *reinterpret_cast<const float4*>(Sg + row * AS + c8 * 8 + 4);
        uint4 o;
        *reinterpret_cast<__half2*>(&o.x) = __floats2half2_rn(v0.x, v0.y);
        *reinterpret_cast<__half2*>(&o.y) = __floats2half2_rn(v0.z, v0.w);
        *reinterpret_cast<__half2*>(&o.z) = __floats2half2_rn(v1.x, v1.y);
        *reinterpret_cast<__half2*>(&o.w) = __floats2half2_rn(v1.z, v1.w);
        *reinterpret_cast<uint4*>(Af + row * ASH + c8 * 8) = o;
    }
}

__device__ __forceinline__ void load_a_f16(__half* Af, const __half* __restrict__ A,
                                           int m0, int M, int t) {
    #pragma unroll
    for (int j = 0; j < 8; j++) {
        int lin = t + 256 * j;
        int row = lin >> 4;
        int c8  = lin & 15;
        int gm  = m0 + row;
        if (gm < M) {
            uint4 u = *reinterpret_cast<const uint4*>(A + (size_t)gm * D + c8 * 8);
            *reinterpret_cast<uint4*>(Af + row * ASH + c8 * 8) = u;
        }
    }
}

__device__ __forceinline__ void load_b_tile(__half* Bs, const float* __restrict__ W, int t) {
    #pragma unroll 4
    for (int j = 0; j < 64; j++) {
        int lin = t + 256 * j;
        int k = lin >> 7;
        int n = lin & 127;
        Bs[n * ASH + k] = __float2half_rn(W[(size_t)k * D + n]);
    }
}

// ldmatrix-based fragment loads: 6 LDSM.x4 + 16 MMA per k-step (was 24 LDS.32).
// A x4 matrices (lane groups 0-7/8-15/16-23/24-31): [mlo,klo],[mhi,klo],[mlo,khi],[mhi,khi]
//   -> regs a0..a3 in exactly the mma m16n8k16 A-fragment order.
// B x4 covers 2 n-chunks: [nt,klo],[nt,khi],[nt+1,klo],[nt+1,khi] -> b0,b1 per chunk.
__device__ __forceinline__ void mma_compute(float acc[2][8][4], uint32_t AfA, uint32_t BsA,
                                            int wm, int wn, int lane) {
    const uint32_t RB = ASH * 2;  // 272 bytes/row
    uint32_t arow = (uint32_t)(wm + (lane & 7) + ((lane >> 3) & 1) * 8);
    uint32_t acolb = (uint32_t)((lane >> 4) * 16);
    uint32_t aoff0 = AfA + arow * RB + acolb;
    uint32_t aoff1 = aoff0 + 16 * RB;
    uint32_t boff[4];
    #pragma unroll
    for (int p = 0; p < 4; p++) {
        uint32_t brow = (uint32_t)(wn + (2 * p + (lane >> 4)) * 8 + (lane & 7));
        boff[p] = BsA + brow * RB + ((lane >> 3) & 1) * 16;
    }
    #pragma unroll
    for (int k0 = 0; k0 < D; k0 += 16) {
        uint32_t a0[4], a1[4], b[4][4];
        LDSM4(a0, aoff0 + k0 * 2);
        LDSM4(a1, aoff1 + k0 * 2);
        #pragma unroll
        for (int p = 0; p < 4; p++) LDSM4(b[p], boff[p] + k0 * 2);
        #pragma unroll
        for (int p = 0; p < 4; p++) {
            mma_f16(acc[0][2 * p],     a0, b[p][0], b[p][1]);
            mma_f16(acc[1][2 * p],     a1, b[p][0], b[p][1]);
            mma_f16(acc[0][2 * p + 1], a0, b[p][2], b[p][3]);
            mma_f16(acc[1][2 * p + 1], a1, b[p][2], b[p][3]);
        }
    }
}

template <int RELU, int ADDC, int WH16>
__device__ __forceinline__ void epilogue(float acc[2][8][4], float* __restrict__ C,
                                         __half* __restrict__ Ch,
                                         const float* s_bias, int m0, int M,
                                         int wm, int wn, int g, int tig) {
    #pragma unroll
    for (int mt = 0; mt < 2; mt++) {
        #pragma unroll
        for (int half_ = 0; half_ < 2; half_++) {
            int gm = m0 + wm + mt * 16 + g + half_ * 8;
            if (gm >= M) continue;
            #pragma unroll
            for (int nt = 0; nt < 8; nt++) {
                int c = wn + nt * 8 + 2 * tig;
                float x = acc[mt][nt][half_ * 2 + 0] + s_bias[c];
                float y = acc[mt][nt][half_ * 2 + 1] + s_bias[c + 1];
                if (ADDC) {
                    float2 pv = *reinterpret_cast<const float2*>(C + (size_t)gm * D + c);
                    x += pv.x; y += pv.y;
                }
                if (RELU) { x = fmaxf(x, 0.f); y = fmaxf(y, 0.f); }
                if (WH16) {
                    __half2 hv = __floats2half2_rn(x, y);
                    *reinterpret_cast<__half2*>(Ch + (size_t)gm * D + c) = hv;
                } else {
                    *reinterpret_cast<float2*>(C + (size_t)gm * D + c) = make_float2(x, y);
                }
            }
        }
    }
}

template <int RELU, int ADDC, int AH16, int WH16>
__global__ void __launch_bounds__(256, 1)
tc_gemm_kernel(const void* __restrict__ Ain, const float* __restrict__ B1,
               const float* __restrict__ bias1, float* __restrict__ C,
               __half* __restrict__ Ch, int M) {
    extern __shared__ char dsm[];
    __shared__ float s_bias[D];

    __half* Bs = reinterpret_cast<__half*>(dsm);
    __half* Af = reinterpret_cast<__half*>(dsm + 128 * ASH * 2);
    float*  Sg = reinterpret_cast<float*>(dsm + 2 * 128 * ASH * 2);

    const int t    = threadIdx.x;
    const int w    = t >> 5;
    const int lane = t & 31;
    const int g    = lane >> 2;
    const int tig  = lane & 3;
    const int wm   = (w >> 1) * 32;
    const int wn   = (w & 1) * 64;

    const uint32_t AfA = smem_u32(Af);
    const uint32_t BsA = smem_u32(Bs);

    if (t < D) s_bias[t] = bias1[t];
    load_b_tile(Bs, B1, t);

    const int ntiles = (M + 127) >> 7;
    float acc[2][8][4];

    if (AH16) {
        const __half* A = (const __half*)Ain;
        __syncthreads();
        for (int tile = blockIdx.x; tile < ntiles; tile += gridDim.x) {
            load_a_f16(Af, A, tile << 7, M, t);
            __syncthreads();
            #pragma unroll
            for (int i = 0; i < 2; i++)
                #pragma unroll
                for (int j = 0; j < 8; j++)
                    #pragma unroll
                    for (int q = 0; q < 4; q++) acc[i][j][q] = 0.f;
            mma_compute(acc, AfA, BsA, wm, wn, lane);
            epilogue<RELU, ADDC, WH16>(acc, C, Ch, s_bias, tile << 7, M, wm, wn, g, tig);
            __syncthreads();
        }
    } else {
        const float* A = (const float*)Ain;
        int tile = blockIdx.x;
        if (tile < ntiles) cp_a_tile(Sg, A, tile << 7, M, t);
        CP_COMMIT();
        __syncthreads();
        for (; tile < ntiles; tile += gridDim.x) {
            CP_WAIT0();
            __syncthreads();
            convert_stage(Sg, Af, t);
            __syncthreads();
            int nt2 = tile + gridDim.x;
            if (nt2 < ntiles) cp_a_tile(Sg, A, nt2 << 7, M, t);
            CP_COMMIT();
            #pragma unroll
            for (int i = 0; i < 2; i++)
                #pragma unroll
                for (int j = 0; j < 8; j++)
                    #pragma unroll
                    for (int q = 0; q < 4; q++) acc[i][j][q] = 0.f;
            mma_compute(acc, AfA, BsA, wm, wn, lane);
            epilogue<RELU, ADDC, WH16>(acc, C, Ch, s_bias, tile << 7, M, wm, wn, g, tig);
            __syncthreads();
        }
    }
}

// ---------------- launch ----------------
extern "C" void kernel_launch(void* const* d_in, const int* in_sizes, int n_in,
                              void* d_out, int out_size) {
    const float* features = (const float*)d_in[0];
    const int*   src0     = (const int*)d_in[1];
    const int*   dst0     = (const int*)d_in[2];
    const int*   src1     = (const int*)d_in[3];
    const int*   dst1     = (const int*)d_in[4];
    const float* W_init   = (const float*)d_in[5];
    const float* b_init   = (const float*)d_in[6];
    const float* W_self   = (const float*)d_in[7];
    const float* b_self   = (const float*)d_in[8];
    const float* W_neigh  = (const float*)d_in[9];
    const float* b_neigh  = (const float*)d_in[10];
    float*       out      = (float*)d_out;

    float *h1, *agg0, *agg1;
    __half *h0h, *h1h;
    int *off0, *esrc0, *off1, *esrc1;
    cudaGetSymbolAddress((void**)&h1, g_h1);
    cudaGetSymbolAddress((void**)&agg0, g_agg0);
    cudaGetSymbolAddress((void**)&agg1, g_agg1);
    cudaGetSymbolAddress((void**)&h0h, g_h0h);
    cudaGetSymbolAddress((void**)&h1h, g_h1h);
    cudaGetSymbolAddress((void**)&off0, g_off0);
    cudaGetSymbolAddress((void**)&esrc0, g_esrc0);
    cudaGetSymbolAddress((void**)&off1, g_off1);
    cudaGetSymbolAddress((void**)&esrc1, g_esrc1);

    const int SMEM_BYTES = 2 * 128 * ASH * 2 + 128 * AS * 4;  // 137216
    static bool s_init = false;
    static cudaStream_t s_side;
    static cudaEvent_t ev_fork, ev_csr, ev_h0, ev_self2, ev_h1, ev_self3;
    if (!s_init) {
        cudaFuncSetAttribute(tc_gemm_kernel<1, 0, 0, 1>, cudaFuncAttributeMaxDynamicSharedMemorySize, SMEM_BYTES);
        cudaFuncSetAttribute(tc_gemm_kernel<0, 0, 1, 0>, cudaFuncAttributeMaxDynamicSharedMemorySize, SMEM_BYTES);
        cudaFuncSetAttribute(tc_gemm_kernel<1, 1, 0, 1>, cudaFuncAttributeMaxDynamicSharedMemorySize, SMEM_BYTES);
        cudaFuncSetAttribute(tc_gemm_kernel<0, 1, 0, 0>, cudaFuncAttributeMaxDynamicSharedMemorySize, SMEM_BYTES);
        cudaStreamCreateWithFlags(&s_side, cudaStreamNonBlocking);
        cudaEventCreateWithFlags(&ev_fork, cudaEventDisableTiming);
        cudaEventCreateWithFlags(&ev_csr, cudaEventDisableTiming);
        cudaEventCreateWithFlags(&ev_h0, cudaEventDisableTiming);
        cudaEventCreateWithFlags(&ev_self2, cudaEventDisableTiming);
        cudaEventCreateWithFlags(&ev_h1, cudaEventDisableTiming);
        cudaEventCreateWithFlags(&ev_self3, cudaEventDisableTiming);
        s_init = true;
    }

    // ---- fork: CSR chain on side stream, GEMM1 on main stream (GEMM1 stays launch #4) ----
    cudaEventRecord(ev_fork, 0);
    cudaStreamWaitEvent(s_side, ev_fork, 0);

    zero_counts_kernel<<<(NDST0 + 255) / 256, 256, 0, s_side>>>();           // #1
    hist_kernel<<<(E0 + 255) / 256, 256, 0, s_side>>>(dst0, dst1);           // #2
    scan_blocks_kernel<<<NB0 + NB1, 1024, 0, s_side>>>();                    // #3

    tc_gemm_kernel<1, 0, 0, 1><<<148, 256, SMEM_BYTES>>>(                    // #4 (profiled)
        features, W_init, b_init, nullptr, h0h, NSRC0);
    cudaEventRecord(ev_h0, 0);

    scan_apply_kernel<<<NB0 + NB1, 1024, 0, s_side>>>();                     // #5
    scatter_kernel<<<(E0 + 255) / 256, 256, 0, s_side>>>(src0, dst0, src1, dst1);  // #6
    cudaEventRecord(ev_csr, s_side);

    cudaStreamWaitEvent(s_side, ev_h0, 0);
    tc_gemm_kernel<0, 0, 1, 0><<<148, 256, SMEM_BYTES, s_side>>>(
        h0h, W_self, b_self, h1, nullptr, NDST0);
    cudaEventRecord(ev_self2, s_side);

    cudaStreamWaitEvent(0, ev_csr, 0);
    aggregate_kernel<<<(NDST0 * 32 + 255) / 256, 256>>>(h0h, off0, esrc0, agg0, NDST0);

    cudaStreamWaitEvent(0, ev_self2, 0);
    tc_gemm_kernel<1, 1, 0, 1><<<148, 256, SMEM_BYTES>>>(
        agg0, W_neigh, b_neigh, h1, h1h, NDST0);
    cudaEventRecord(ev_h1, 0);

    cudaStreamWaitEvent(s_side, ev_h1, 0);
    tc_gemm_kernel<0, 0, 1, 0><<<79, 256, SMEM_BYTES, s_side>>>(
        h1h, W_self, b_self, out, nullptr, NDST1);
    cudaEventRecord(ev_self3, s_side);

    aggregate_kernel<<<(NDST1 * 32 + 255) / 256, 256>>>(h1h, off1, esrc1, agg1, NDST1);

    cudaStreamWaitEvent(0, ev_self3, 0);
    tc_gemm_kernel<0, 1, 0, 0><<<79, 256, SMEM_BYTES>>>(
        agg1, W_neigh, b_neigh, out, nullptr, NDST1);
}

// round 13
// speedup vs baseline: 1.1078x; 1.1078x over previous
#include <cuda_runtime.h>
#include <cuda_fp16.h>
#include <cstdint>
#include <cstddef>

// Problem constants (fixed by the reference)
#define NSRC0 200000
#define NDST0 50000
#define NDST1 10000
#define E0    800000
#define E1    160000
#define D     128

#define AS  132  // fp32 stage row stride (floats)
#define ASH 136  // fp16 tile row stride (halves); 272 B/row == 16 B mod 128 -> ldmatrix conflict-free
#define NT  512  // GEMM CTA threads (16 warps)

#define NB0 49  // ceil(50000/1024)
#define NB1 10  // ceil(10000/1024)

// ---------------- device scratch (static globals; no allocation) ----------------
__device__ float g_h1[(size_t)NDST0 * D];    // layer-1 fp32 ADDC partial
__device__ float g_agg0[(size_t)NDST0 * D];
__device__ float g_agg1[(size_t)NDST1 * D];
__device__ __half g_h0h[(size_t)NSRC0 * D];  // h0 lives ONLY in fp16
__device__ __half g_h1h[(size_t)NDST0 * D];  // h1 lives ONLY in fp16

__device__ int g_cnt0[NDST0];
__device__ int g_off0[NDST0 + 1];
__device__ int g_cur0[NDST0];
__device__ int g_esrc0[E0];

__device__ int g_cnt1[NDST1];
__device__ int g_off1[NDST1 + 1];
__device__ int g_cur1[NDST1];
__device__ int g_esrc1[E1];

__device__ int g_bsum[NB0 + NB1];

// ---------------- helpers ----------------
__device__ __forceinline__ uint32_t smem_u32(const void* p) {
    uint32_t a;
    asm("{ .reg .u64 t; cvta.to.shared.u64 t, %1; cvt.u32.u64 %0, t; }" : "=r"(a) : "l"(p));
    return a;
}
#define CP_ASYNC16(dst, src) \
    asm volatile("cp.async.cg.shared.global [%0], [%1], 16;" :: "r"(dst), "l"(src) : "memory")
#define CP_COMMIT() asm volatile("cp.async.commit_group;" ::: "memory")
#define CP_WAIT0()  asm volatile("cp.async.wait_group 0;" ::: "memory")

#define LDSM4(r, addr) \
    asm volatile("ldmatrix.sync.aligned.m8n8.x4.shared.b16 {%0,%1,%2,%3}, [%4];" \
                 : "=r"((r)[0]), "=r"((r)[1]), "=r"((r)[2]), "=r"((r)[3]) : "r"(addr))

// m16n8k16 fp16 MMA, fp32 accumulate
__device__ __forceinline__ void mma_f16(float d[4], const uint32_t a[4], uint32_t b0, uint32_t b1) {
    asm volatile(
        "mma.sync.aligned.m16n8k16.row.col.f32.f16.f16.f32 "
        "{%0,%1,%2,%3}, {%4,%5,%6,%7}, {%8,%9}, {%0,%1,%2,%3};"
        : "+f"(d[0]), "+f"(d[1]), "+f"(d[2]), "+f"(d[3])
        : "r"(a[0]), "r"(a[1]), "r"(a[2]), "r"(a[3]), "r"(b0), "r"(b1));
}

// ---------------- CSR build ----------------
__global__ void zero_counts_kernel() {
    int i = blockIdx.x * blockDim.x + threadIdx.x;
    if (i < NDST0) g_cnt0[i] = 0;
    if (i < NDST1) g_cnt1[i] = 0;
}
__global__ void hist_kernel(const int* __restrict__ dst0, const int* __restrict__ dst1) {
    int i = blockIdx.x * blockDim.x + threadIdx.x;
    if (i < E0) atomicAdd(&g_cnt0[dst0[i]], 1);
    if (i < E1) atomicAdd(&g_cnt1[dst1[i]], 1);
}

__global__ void scan_blocks_kernel() {
    __shared__ int sums[1024];
    const int b = blockIdx.x;
    const int tid = threadIdx.x;
    const int graph = (b < NB0) ? 0 : 1;
    const int blk = graph ? (b - NB0) : b;
    const int n = graph ? NDST1 : NDST0;
    const int* cnt = graph ? g_cnt1 : g_cnt0;
    int* off = graph ? g_off1 : g_off0;

    const int i = blk * 1024 + tid;
    const int v = (i < n) ? cnt[i] : 0;
    sums[tid] = v;
    __syncthreads();
    #pragma unroll
    for (int d = 1; d < 1024; d <<= 1) {
        int x = (tid >= d) ? sums[tid - d] : 0;
        __syncthreads();
        sums[tid] += x;
        __syncthreads();
    }
    if (i < n) off[i] = sums[tid] - v;
    if (tid == 1023) g_bsum[b] = sums[1023];
}

__global__ void scan_apply_kernel() {
    __shared__ int s_base;
    const int b = blockIdx.x;
    const int tid = threadIdx.x;
    const int graph = (b < NB0) ? 0 : 1;
    const int blk = graph ? (b - NB0) : b;
    const int n = graph ? NDST1 : NDST0;
    int* off = graph ? g_off1 : g_off0;
    int* cur = graph ? g_cur1 : g_cur0;
    if (tid == 0) {
        int base = 0;
        int start = graph ? NB0 : 0;
        for (int j = start; j < b; j++) base += g_bsum[j];
        s_base = base;
        if (b == 0) g_off0[NDST0] = E0;
        if (b == NB0) g_off1[NDST1] = E1;
    }
    __syncthreads();
    const int base = s_base;
    const int i = blk * 1024 + tid;
    if (i < n) {
        int o = off[i] + base;
        off[i] = o;
        cur[i] = o;
    }
}

__global__ void scatter_kernel(const int* __restrict__ src0, const int* __restrict__ dst0,
                               const int* __restrict__ src1, const int* __restrict__ dst1) {
    int i = blockIdx.x * blockDim.x + threadIdx.x;
    if (i < E0) { int pos = atomicAdd(&g_cur0[dst0[i]], 1); g_esrc0[pos] = src0[i]; }
    if (i < E1) { int pos = atomicAdd(&g_cur1[dst1[i]], 1); g_esrc1[pos] = src1[i]; }
}

// ---------------- mean aggregation over fp16 messages, fp32 accumulate ----------------
__global__ void aggregate_kernel(const __half* __restrict__ hh,
                                 const int* __restrict__ off,
                                 const int* __restrict__ esrc, float* __restrict__ agg,
                                 int ndst) {
    int gw = (blockIdx.x * blockDim.x + threadIdx.x) >> 5;
    int lane = threadIdx.x & 31;
    if (gw >= ndst) return;
    int s = off[gw], e = off[gw + 1];
    float4 acc = make_float4(0.f, 0.f, 0.f, 0.f);
    float4 acc2 = make_float4(0.f, 0.f, 0.f, 0.f);
    int i = s;
    for (; i + 2 <= e; i += 2) {
        const uint2* r0 = reinterpret_cast<const uint2*>(hh + (size_t)esrc[i] * D);
        const uint2* r1 = reinterpret_cast<const uint2*>(hh + (size_t)esrc[i + 1] * D);
        uint2 u0 = __ldg(&r0[lane]);
        uint2 u1 = __ldg(&r1[lane]);
        float2 p0 = __half22float2(*reinterpret_cast<__half2*>(&u0.x));
        float2 p1 = __half22float2(*reinterpret_cast<__half2*>(&u0.y));
        float2 q0 = __half22float2(*reinterpret_cast<__half2*>(&u1.x));
        float2 q1 = __half22float2(*reinterpret_cast<__half2*>(&u1.y));
        acc.x += p0.x;  acc.y += p0.y;  acc.z += p1.x;  acc.w += p1.y;
        acc2.x += q0.x; acc2.y += q0.y; acc2.z += q1.x; acc2.w += q1.y;
    }
    if (i < e) {
        const uint2* r0 = reinterpret_cast<const uint2*>(hh + (size_t)esrc[i] * D);
        uint2 u0 = __ldg(&r0[lane]);
        float2 p0 = __half22float2(*reinterpret_cast<__half2*>(&u0.x));
        float2 p1 = __half22float2(*reinterpret_cast<__half2*>(&u0.y));
        acc.x += p0.x; acc.y += p0.y; acc.z += p1.x; acc.w += p1.y;
    }
    acc.x += acc2.x; acc.y += acc2.y; acc.z += acc2.z; acc.w += acc2.w;
    float inv = 1.0f / fmaxf((float)(e - s), 1.0f);
    acc.x *= inv; acc.y *= inv; acc.z *= inv; acc.w *= inv;
    reinterpret_cast<float4*>(agg + (size_t)gw * D)[lane] = acc;
}

// ---------------- fp16 HMMA GEMM (512 thr, 16 warps, warp tile 16x64) ----------------
__device__ __forceinline__ void cp_a_tile(float* Sg, const float* __restrict__ A,
                                          int m0, int M, int t) {
    uint32_t sb = smem_u32(Sg);
    #pragma unroll
    for (int j = 0; j < 8; j++) {
        int lin = t + NT * j;       // 0..4095
        int row = lin >> 5;
        int c4  = lin & 31;
        int gm  = m0 + row;
        if (gm < M)
            CP_ASYNC16(sb + (uint32_t)(row * AS + c4 * 4) * 4,
                       A + (size_t)gm * D + c4 * 4);
    }
}

__device__ __forceinline__ void convert_stage(const float* Sg, __half* Af, int t) {
    #pragma unroll
    for (int j = 0; j < 4; j++) {
        int lin = t + NT * j;       // 0..2047
        int row = lin >> 4;
        int c8  = lin & 15;
        float4 v0 = *reinterpret_cast<const float4*>(Sg + row * AS + c8 * 8);
        float4 v1 = *reinterpret_cast<const float4*>(Sg + row * AS + c8 * 8 + 4);
        uint4 o;
        *reinterpret_cast<__half2*>(&o.x) = __floats2half2_rn(v0.x, v0.y);
        *reinterpret_cast<__half2*>(&o.y) = __floats2half2_rn(v0.z, v0.w);
        *reinterpret_cast<__half2*>(&o.z) = __floats2half2_rn(v1.x, v1.y);
        *reinterpret_cast<__half2*>(&o.w) = __floats2half2_rn(v1.z, v1.w);
        *reinterpret_cast<uint4*>(Af + row * ASH + c8 * 8) = o;
    }
}

__device__ __forceinline__ void load_a_f16(__half* Af, const __half* __restrict__ A,
                                           int m0, int M, int t) {
    #pragma unroll
    for (int j = 0; j < 4; j++) {
        int lin = t + NT * j;
        int row = lin >> 4;
        int c8  = lin & 15;
        int gm  = m0 + row;
        if (gm < M) {
            uint4 u = *reinterpret_cast<const uint4*>(A + (size_t)gm * D + c8 * 8);
            *reinterpret_cast<uint4*>(Af + row * ASH + c8 * 8) = u;
        }
    }
}

__device__ __forceinline__ void load_b_tile(__half* Bs, const float* __restrict__ W, int t) {
    #pragma unroll 4
    for (int j = 0; j < 32; j++) {
        int lin = t + NT * j;
        int k = lin >> 7;
        int n = lin & 127;
        Bs[n * ASH + k] = __float2half_rn(W[(size_t)k * D + n]);
    }
}

// Per warp: 16x64 tile. Per k-step: 1 A-LDSM.x4 + 4 B-LDSM.x4 + 8 MMA.
__device__ __forceinline__ void mma_compute(float acc[8][4], uint32_t AfA, uint32_t BsA,
                                            int wm, int wn, int lane) {
    const uint32_t RB = ASH * 2;  // 272 bytes/row
    uint32_t arow = (uint32_t)(wm + (lane & 7) + ((lane >> 3) & 1) * 8);
    uint32_t aoff = AfA + arow * RB + (uint32_t)((lane >> 4) * 16);
    uint32_t boff[4];
    #pragma unroll
    for (int p = 0; p < 4; p++) {
        uint32_t brow = (uint32_t)(wn + (2 * p + (lane >> 4)) * 8 + (lane & 7));
        boff[p] = BsA + brow * RB + ((lane >> 3) & 1) * 16;
    }
    #pragma unroll
    for (int k0 = 0; k0 < D; k0 += 16) {
        uint32_t a0[4], b[4][4];
        LDSM4(a0, aoff + k0 * 2);
        #pragma unroll
        for (int p = 0; p < 4; p++) LDSM4(b[p], boff[p] + k0 * 2);
        #pragma unroll
        for (int p = 0; p < 4; p++) {
            mma_f16(acc[2 * p],     a0, b[p][0], b[p][1]);
            mma_f16(acc[2 * p + 1], a0, b[p][2], b[p][3]);
        }
    }
}

template <int RELU, int ADDC, int WH16>
__device__ __forceinline__ void epilogue(float acc[8][4], float* __restrict__ C,
                                         __half* __restrict__ Ch,
                                         const float* s_bias, int m0, int M,
                                         int wm, int wn, int g, int tig) {
    #pragma unroll
    for (int half_ = 0; half_ < 2; half_++) {
        int gm = m0 + wm + g + half_ * 8;
        if (gm >= M) continue;
        #pragma unroll
        for (int nt = 0; nt < 8; nt++) {
            int c = wn + nt * 8 + 2 * tig;
            float x = acc[nt][half_ * 2 + 0] + s_bias[c];
            float y = acc[nt][half_ * 2 + 1] + s_bias[c + 1];
            if (ADDC) {
                float2 pv = *reinterpret_cast<const float2*>(C + (size_t)gm * D + c);
                x += pv.x; y += pv.y;
            }
            if (RELU) { x = fmaxf(x, 0.f); y = fmaxf(y, 0.f); }
            if (WH16) {
                __half2 hv = __floats2half2_rn(x, y);
                *reinterpret_cast<__half2*>(Ch + (size_t)gm * D + c) = hv;
            } else {
                *reinterpret_cast<float2*>(C + (size_t)gm * D + c) = make_float2(x, y);
            }
        }
    }
}

template <int RELU, int ADDC, int AH16, int WH16>
__global__ void __launch_bounds__(NT, 1)
tc_gemm_kernel(const void* __restrict__ Ain, const float* __restrict__ B1,
               const float* __restrict__ bias1, float* __restrict__ C,
               __half* __restrict__ Ch, int M) {
    extern __shared__ char dsm[];
    __shared__ float s_bias[D];

    __half* Bs = reinterpret_cast<__half*>(dsm);
    __half* Af = reinterpret_cast<__half*>(dsm + 128 * ASH * 2);
    float*  Sg = reinterpret_cast<float*>(dsm + 2 * 128 * ASH * 2);

    const int t    = threadIdx.x;
    const int w    = t >> 5;
    const int lane = t & 31;
    const int g    = lane >> 2;
    const int tig  = lane & 3;
    const int wm   = (w >> 1) * 16;   // 8 M-groups of 16 rows
    const int wn   = (w & 1) * 64;    // 2 N-halves

    const uint32_t AfA = smem_u32(Af);
    const uint32_t BsA = smem_u32(Bs);

    if (t < D) s_bias[t] = bias1[t];
    load_b_tile(Bs, B1, t);

    const int ntiles = (M + 127) >> 7;
    float acc[8][4];

    if (AH16) {
        const __half* A = (const __half*)Ain;
        __syncthreads();
        for (int tile = blockIdx.x; tile < ntiles; tile += gridDim.x) {
            load_a_f16(Af, A, tile << 7, M, t);
            __syncthreads();
            #pragma unroll
            for (int j = 0; j < 8; j++)
                #pragma unroll
                for (int q = 0; q < 4; q++) acc[j][q] = 0.f;
            mma_compute(acc, AfA, BsA, wm, wn, lane);
            epilogue<RELU, ADDC, WH16>(acc, C, Ch, s_bias, tile << 7, M, wm, wn, g, tig);
            __syncthreads();
        }
    } else {
        const float* A = (const float*)Ain;
        int tile = blockIdx.x;
        if (tile < ntiles) cp_a_tile(Sg, A, tile << 7, M, t);
        CP_COMMIT();
        __syncthreads();
        for (; tile < ntiles; tile += gridDim.x) {
            CP_WAIT0();
            __syncthreads();
            convert_stage(Sg, Af, t);
            __syncthreads();
            int nt2 = tile + gridDim.x;
            if (nt2 < ntiles) cp_a_tile(Sg, A, nt2 << 7, M, t);
            CP_COMMIT();
            #pragma unroll
            for (int j = 0; j < 8; j++)
                #pragma unroll
                for (int q = 0; q < 4; q++) acc[j][q] = 0.f;
            mma_compute(acc, AfA, BsA, wm, wn, lane);
            epilogue<RELU, ADDC, WH16>(acc, C, Ch, s_bias, tile << 7, M, wm, wn, g, tig);
            __syncthreads();
        }
    }
}

// ---------------- launch ----------------
extern "C" void kernel_launch(void* const* d_in, const int* in_sizes, int n_in,
                              void* d_out, int out_size) {
    const float* features = (const float*)d_in[0];
    const int*   src0     = (const int*)d_in[1];
    const int*   dst0     = (const int*)d_in[2];
    const int*   src1     = (const int*)d_in[3];
    const int*   dst1     = (const int*)d_in[4];
    const float* W_init   = (const float*)d_in[5];
    const float* b_init   = (const float*)d_in[6];
    const float* W_self   = (const float*)d_in[7];
    const float* b_self   = (const float*)d_in[8];
    const float* W_neigh  = (const float*)d_in[9];
    const float* b_neigh  = (const float*)d_in[10];
    float*       out      = (float*)d_out;

    float *h1, *agg0, *agg1;
    __half *h0h, *h1h;
    int *off0, *esrc0, *off1, *esrc1;
    cudaGetSymbolAddress((void**)&h1, g_h1);
    cudaGetSymbolAddress((void**)&agg0, g_agg0);
    cudaGetSymbolAddress((void**)&agg1, g_agg1);
    cudaGetSymbolAddress((void**)&h0h, g_h0h);
    cudaGetSymbolAddress((void**)&h1h, g_h1h);
    cudaGetSymbolAddress((void**)&off0, g_off0);
    cudaGetSymbolAddress((void**)&esrc0, g_esrc0);
    cudaGetSymbolAddress((void**)&off1, g_off1);
    cudaGetSymbolAddress((void**)&esrc1, g_esrc1);

    const int SMEM_BYTES = 2 * 128 * ASH * 2 + 128 * AS * 4;  // 137216
    static bool s_init = false;
    static cudaStream_t s_side;
    static cudaEvent_t ev_fork, ev_csr, ev_h0, ev_self2, ev_h1, ev_self3;
    if (!s_init) {
        cudaFuncSetAttribute(tc_gemm_kernel<1, 0, 0, 1>, cudaFuncAttributeMaxDynamicSharedMemorySize, SMEM_BYTES);
        cudaFuncSetAttribute(tc_gemm_kernel<0, 0, 1, 0>, cudaFuncAttributeMaxDynamicSharedMemorySize, SMEM_BYTES);
        cudaFuncSetAttribute(tc_gemm_kernel<1, 1, 0, 1>, cudaFuncAttributeMaxDynamicSharedMemorySize, SMEM_BYTES);
        cudaFuncSetAttribute(tc_gemm_kernel<0, 1, 0, 0>, cudaFuncAttributeMaxDynamicSharedMemorySize, SMEM_BYTES);
        cudaStreamCreateWithFlags(&s_side, cudaStreamNonBlocking);
        cudaEventCreateWithFlags(&ev_fork, cudaEventDisableTiming);
        cudaEventCreateWithFlags(&ev_csr, cudaEventDisableTiming);
        cudaEventCreateWithFlags(&ev_h0, cudaEventDisableTiming);
        cudaEventCreateWithFlags(&ev_self2, cudaEventDisableTiming);
        cudaEventCreateWithFlags(&ev_h1, cudaEventDisableTiming);
        cudaEventCreateWithFlags(&ev_self3, cudaEventDisableTiming);
        s_init = true;
    }

    // ---- fork: CSR chain on side stream, GEMM1 on main stream (GEMM1 stays launch #4) ----
    cudaEventRecord(ev_fork, 0);
    cudaStreamWaitEvent(s_side, ev_fork, 0);

    zero_counts_kernel<<<(NDST0 + 255) / 256, 256, 0, s_side>>>();           // #1
    hist_kernel<<<(E0 + 255) / 256, 256, 0, s_side>>>(dst0, dst1);           // #2
    scan_blocks_kernel<<<NB0 + NB1, 1024, 0, s_side>>>();                    // #3

    tc_gemm_kernel<1, 0, 0, 1><<<148, NT, SMEM_BYTES>>>(                     // #4 (profiled)
        features, W_init, b_init, nullptr, h0h, NSRC0);
    cudaEventRecord(ev_h0, 0);

    scan_apply_kernel<<<NB0 + NB1, 1024, 0, s_side>>>();                     // #5
    scatter_kernel<<<(E0 + 255) / 256, 256, 0, s_side>>>(src0, dst0, src1, dst1);  // #6
    cudaEventRecord(ev_csr, s_side);

    cudaStreamWaitEvent(s_side, ev_h0, 0);
    tc_gemm_kernel<0, 0, 1, 0><<<148, NT, SMEM_BYTES, s_side>>>(
        h0h, W_self, b_self, h1, nullptr, NDST0);
    cudaEventRecord(ev_self2, s_side);

    cudaStreamWaitEvent(0, ev_csr, 0);
    aggregate_kernel<<<(NDST0 * 32 + 255) / 256, 256>>>(h0h, off0, esrc0, agg0, NDST0);

    cudaStreamWaitEvent(0, ev_self2, 0);
    tc_gemm_kernel<1, 1, 0, 1><<<148, NT, SMEM_BYTES>>>(
        agg0, W_neigh, b_neigh, h1, h1h, NDST0);
    cudaEventRecord(ev_h1, 0);

    cudaStreamWaitEvent(s_side, ev_h1, 0);
    tc_gemm_kernel<0, 0, 1, 0><<<79, NT, SMEM_BYTES, s_side>>>(
        h1h, W_self, b_self, out, nullptr, NDST1);
    cudaEventRecord(ev_self3, s_side);

    aggregate_kernel<<<(NDST1 * 32 + 255) / 256, 256>>>(h1h, off1, esrc1, agg1, NDST1);

    cudaStreamWaitEvent(0, ev_self3, 0);
    tc_gemm_kernel<0, 1, 0, 0><<<79, NT, SMEM_BYTES>>>(
        agg1, W_neigh, b_neigh, out, nullptr, NDST1);
}

// round 14
// speedup vs baseline: 1.2103x; 1.0926x over previous
#include <cuda_runtime.h>
#include <cuda_fp16.h>
#include <cstdint>
#include <cstddef>

// Problem constants (fixed by the reference)
#define NSRC0 200000
#define NDST0 50000
#define NDST1 10000
#define E0    800000
#define E1    160000
#define D     128

#define ASH 136  // fp16 tile row stride (halves); 272 B/row == 16 B mod 128 -> ldmatrix conflict-free
#define NT  512  // GEMM CTA threads (16 warps), warp grid 4(M) x 4(N), warp tile 32x32

#define NB0 49  // ceil(50000/1024)
#define NB1 10  // ceil(10000/1024)

// ---------------- device scratch (static globals; no allocation) ----------------
__device__ float g_h1[(size_t)NDST0 * D];    // layer-1 fp32 ADDC partial
__device__ float g_agg0[(size_t)NDST0 * D];
__device__ float g_agg1[(size_t)NDST1 * D];
__device__ __half g_h0h[(size_t)NSRC0 * D];  // h0 lives ONLY in fp16
__device__ __half g_h1h[(size_t)NDST0 * D];  // h1 lives ONLY in fp16

__device__ int g_cnt0[NDST0];
__device__ int g_off0[NDST0 + 1];
__device__ int g_cur0[NDST0];
__device__ int g_esrc0[E0];

__device__ int g_cnt1[NDST1];
__device__ int g_off1[NDST1 + 1];
__device__ int g_cur1[NDST1];
__device__ int g_esrc1[E1];

__device__ int g_bsum[NB0 + NB1];

// ---------------- helpers ----------------
__device__ __forceinline__ uint32_t smem_u32(const void* p) {
    uint32_t a;
    asm("{ .reg .u64 t; cvta.to.shared.u64 t, %1; cvt.u32.u64 %0, t; }" : "=r"(a) : "l"(p));
    return a;
}
#define LDSM4(r, addr) \
    asm volatile("ldmatrix.sync.aligned.m8n8.x4.shared.b16 {%0,%1,%2,%3}, [%4];" \
                 : "=r"((r)[0]), "=r"((r)[1]), "=r"((r)[2]), "=r"((r)[3]) : "r"(addr))

// m16n8k16 fp16 MMA, fp32 accumulate
__device__ __forceinline__ void mma_f16(float d[4], const uint32_t a[4], uint32_t b0, uint32_t b1) {
    asm volatile(
        "mma.sync.aligned.m16n8k16.row.col.f32.f16.f16.f32 "
        "{%0,%1,%2,%3}, {%4,%5,%6,%7}, {%8,%9}, {%0,%1,%2,%3};"
        : "+f"(d[0]), "+f"(d[1]), "+f"(d[2]), "+f"(d[3])
        : "r"(a[0]), "r"(a[1]), "r"(a[2]), "r"(a[3]), "r"(b0), "r"(b1));
}

// ---------------- CSR build ----------------
__global__ void zero_counts_kernel() {
    int i = blockIdx.x * blockDim.x + threadIdx.x;
    if (i < NDST0) g_cnt0[i] = 0;
    if (i < NDST1) g_cnt1[i] = 0;
}
__global__ void hist_kernel(const int* __restrict__ dst0, const int* __restrict__ dst1) {
    int i = blockIdx.x * blockDim.x + threadIdx.x;
    if (i < E0) atomicAdd(&g_cnt0[dst0[i]], 1);
    if (i < E1) atomicAdd(&g_cnt1[dst1[i]], 1);
}

__global__ void scan_blocks_kernel() {
    __shared__ int sums[1024];
    const int b = blockIdx.x;
    const int tid = threadIdx.x;
    const int graph = (b < NB0) ? 0 : 1;
    const int blk = graph ? (b - NB0) : b;
    const int n = graph ? NDST1 : NDST0;
    const int* cnt = graph ? g_cnt1 : g_cnt0;
    int* off = graph ? g_off1 : g_off0;

    const int i = blk * 1024 + tid;
    const int v = (i < n) ? cnt[i] : 0;
    sums[tid] = v;
    __syncthreads();
    #pragma unroll
    for (int d = 1; d < 1024; d <<= 1) {
        int x = (tid >= d) ? sums[tid - d] : 0;
        __syncthreads();
        sums[tid] += x;
        __syncthreads();
    }
    if (i < n) off[i] = sums[tid] - v;
    if (tid == 1023) g_bsum[b] = sums[1023];
}

__global__ void scan_apply_kernel() {
    __shared__ int s_base;
    const int b = blockIdx.x;
    const int tid = threadIdx.x;
    const int graph = (b < NB0) ? 0 : 1;
    const int blk = graph ? (b - NB0) : b;
    const int n = graph ? NDST1 : NDST0;
    int* off = graph ? g_off1 : g_off0;
    int* cur = graph ? g_cur1 : g_cur0;
    if (tid == 0) {
        int base = 0;
        int start = graph ? NB0 : 0;
        for (int j = start; j < b; j++) base += g_bsum[j];
        s_base = base;
        if (b == 0) g_off0[NDST0] = E0;
        if (b == NB0) g_off1[NDST1] = E1;
    }
    __syncthreads();
    const int base = s_base;
    const int i = blk * 1024 + tid;
    if (i < n) {
        int o = off[i] + base;
        off[i] = o;
        cur[i] = o;
    }
}

__global__ void scatter_kernel(const int* __restrict__ src0, const int* __restrict__ dst0,
                               const int* __restrict__ src1, const int* __restrict__ dst1) {
    int i = blockIdx.x * blockDim.x + threadIdx.x;
    if (i < E0) { int pos = atomicAdd(&g_cur0[dst0[i]], 1); g_esrc0[pos] = src0[i]; }
    if (i < E1) { int pos = atomicAdd(&g_cur1[dst1[i]], 1); g_esrc1[pos] = src1[i]; }
}

// ---------------- mean aggregation over fp16 messages, fp32 accumulate ----------------
__global__ void aggregate_kernel(const __half* __restrict__ hh,
                                 const int* __restrict__ off,
                                 const int* __restrict__ esrc, float* __restrict__ agg,
                                 int ndst) {
    int gw = (blockIdx.x * blockDim.x + threadIdx.x) >> 5;
    int lane = threadIdx.x & 31;
    if (gw >= ndst) return;
    int s = off[gw], e = off[gw + 1];
    float4 acc = make_float4(0.f, 0.f, 0.f, 0.f);
    float4 acc2 = make_float4(0.f, 0.f, 0.f, 0.f);
    int i = s;
    for (; i + 2 <= e; i += 2) {
        const uint2* r0 = reinterpret_cast<const uint2*>(hh + (size_t)esrc[i] * D);
        const uint2* r1 = reinterpret_cast<const uint2*>(hh + (size_t)esrc[i + 1] * D);
        uint2 u0 = __ldg(&r0[lane]);
        uint2 u1 = __ldg(&r1[lane]);
        float2 p0 = __half22float2(*reinterpret_cast<__half2*>(&u0.x));
        float2 p1 = __half22float2(*reinterpret_cast<__half2*>(&u0.y));
        float2 q0 = __half22float2(*reinterpret_cast<__half2*>(&u1.x));
        float2 q1 = __half22float2(*reinterpret_cast<__half2*>(&u1.y));
        acc.x += p0.x;  acc.y += p0.y;  acc.z += p1.x;  acc.w += p1.y;
        acc2.x += q0.x; acc2.y += q0.y; acc2.z += q1.x; acc2.w += q1.y;
    }
    if (i < e) {
        const uint2* r0 = reinterpret_cast<const uint2*>(hh + (size_t)esrc[i] * D);
        uint2 u0 = __ldg(&r0[lane]);
        float2 p0 = __half22float2(*reinterpret_cast<__half2*>(&u0.x));
        float2 p1 = __half22float2(*reinterpret_cast<__half2*>(&u0.y));
        acc.x += p0.x; acc.y += p0.y; acc.z += p1.x; acc.w += p1.y;
    }
    acc.x += acc2.x; acc.y += acc2.y; acc.z += acc2.z; acc.w += acc2.w;
    float inv = 1.0f / fmaxf((float)(e - s), 1.0f);
    acc.x *= inv; acc.y *= inv; acc.z *= inv; acc.w *= inv;
    reinterpret_cast<float4*>(agg + (size_t)gw * D)[lane] = acc;
}

// ---------------- fp16 HMMA GEMM (512 thr, warp grid 4x4, warp tile 32x32) ----------------
// fp32-A path: LDG -> regs -> fp16 STS (no smem stage); next-tile LDG overlaps MMA.
// AH16 path: direct fp16 tile loads.

// LDG fp32 tile into registers (8 float4 per thread)
__device__ __forceinline__ void ldg_tile(float4 buf[8], const float* __restrict__ A,
                                         int m0, int M, int t) {
    #pragma unroll
    for (int j = 0; j < 8; j++) {
        int lin = t + NT * j;      // 0..4095
        int row = lin >> 5;        // 0..127
        int c4  = lin & 31;        // float4 chunk
        int gm  = m0 + row;
        if (gm < M)
            buf[j] = *reinterpret_cast<const float4*>(A + (size_t)gm * D + c4 * 4);
    }
}

// regs -> fp16 smem tile (8B STS each, conflict-free)
__device__ __forceinline__ void sts_convert(const float4 buf[8], __half* Af,
                                            int m0, int M, int t) {
    #pragma unroll
    for (int j = 0; j < 8; j++) {
        int lin = t + NT * j;
        int row = lin >> 5;
        int c4  = lin & 31;
        if (m0 + row < M) {
            float4 v = buf[j];
            uint2 o;
            *reinterpret_cast<__half2*>(&o.x) = __floats2half2_rn(v.x, v.y);
            *reinterpret_cast<__half2*>(&o.y) = __floats2half2_rn(v.z, v.w);
            *reinterpret_cast<uint2*>(Af + row * ASH + c4 * 4) = o;
        }
    }
}

__device__ __forceinline__ void load_a_f16(__half* Af, const __half* __restrict__ A,
                                           int m0, int M, int t) {
    #pragma unroll
    for (int j = 0; j < 4; j++) {
        int lin = t + NT * j;
        int row = lin >> 4;
        int c8  = lin & 15;
        int gm  = m0 + row;
        if (gm < M) {
            uint4 u = *reinterpret_cast<const uint4*>(A + (size_t)gm * D + c8 * 8);
            *reinterpret_cast<uint4*>(Af + row * ASH + c8 * 8) = u;
        }
    }
}

__device__ __forceinline__ void load_b_tile(__half* Bs, const float* __restrict__ W, int t) {
    #pragma unroll 4
    for (int j = 0; j < 32; j++) {
        int lin = t + NT * j;
        int k = lin >> 7;
        int n = lin & 127;
        Bs[n * ASH + k] = __float2half_rn(W[(size_t)k * D + n]);
    }
}

// Warp tile 32x32. Per k-step: 2 A-LDSM.x4 + 2 B-LDSM.x4 + 8 MMA.
__device__ __forceinline__ void mma_compute(float acc[2][4][4], uint32_t AfA, uint32_t BsA,
                                            int wm, int wn, int lane) {
    const uint32_t RB = ASH * 2;  // 272 bytes/row
    uint32_t arow = (uint32_t)(wm + (lane & 7) + ((lane >> 3) & 1) * 8);
    uint32_t aoff0 = AfA + arow * RB + (uint32_t)((lane >> 4) * 16);
    uint32_t aoff1 = aoff0 + 16 * RB;
    uint32_t boff[2];
    #pragma unroll
    for (int p = 0; p < 2; p++) {
        uint32_t brow = (uint32_t)(wn + (2 * p + (lane >> 4)) * 8 + (lane & 7));
        boff[p] = BsA + brow * RB + ((lane >> 3) & 1) * 16;
    }
    #pragma unroll
    for (int k0 = 0; k0 < D; k0 += 16) {
        uint32_t a0[4], a1[4], b[2][4];
        LDSM4(a0, aoff0 + k0 * 2);
        LDSM4(a1, aoff1 + k0 * 2);
        LDSM4(b[0], boff[0] + k0 * 2);
        LDSM4(b[1], boff[1] + k0 * 2);
        #pragma unroll
        for (int p = 0; p < 2; p++) {
            mma_f16(acc[0][2 * p],     a0, b[p][0], b[p][1]);
            mma_f16(acc[1][2 * p],     a1, b[p][0], b[p][1]);
            mma_f16(acc[0][2 * p + 1], a0, b[p][2], b[p][3]);
            mma_f16(acc[1][2 * p + 1], a1, b[p][2], b[p][3]);
        }
    }
}

template <int RELU, int ADDC, int WH16>
__device__ __forceinline__ void epilogue(float acc[2][4][4], float* __restrict__ C,
                                         __half* __restrict__ Ch,
                                         const float* s_bias, int m0, int M,
                                         int wm, int wn, int g, int tig) {
    #pragma unroll
    for (int mt = 0; mt < 2; mt++) {
        #pragma unroll
        for (int half_ = 0; half_ < 2; half_++) {
            int gm = m0 + wm + mt * 16 + g + half_ * 8;
            if (gm >= M) continue;
            #pragma unroll
            for (int nt = 0; nt < 4; nt++) {
                int c = wn + nt * 8 + 2 * tig;
                float x = acc[mt][nt][half_ * 2 + 0] + s_bias[c];
                float y = acc[mt][nt][half_ * 2 + 1] + s_bias[c + 1];
                if (ADDC) {
                    float2 pv = *reinterpret_cast<const float2*>(C + (size_t)gm * D + c);
                    x += pv.x; y += pv.y;
                }
                if (RELU) { x = fmaxf(x, 0.f); y = fmaxf(y, 0.f); }
                if (WH16) {
                    __half2 hv = __floats2half2_rn(x, y);
                    *reinterpret_cast<__half2*>(Ch + (size_t)gm * D + c) = hv;
                } else {
                    *reinterpret_cast<float2*>(C + (size_t)gm * D + c) = make_float2(x, y);
                }
            }
        }
    }
}

template <int RELU, int ADDC, int AH16, int WH16>
__global__ void __launch_bounds__(NT, 1)
tc_gemm_kernel(const void* __restrict__ Ain, const float* __restrict__ B1,
               const float* __restrict__ bias1, float* __restrict__ C,
               __half* __restrict__ Ch, int M) {
    extern __shared__ char dsm[];
    __shared__ float s_bias[D];

    __half* Bs = reinterpret_cast<__half*>(dsm);
    __half* Af = reinterpret_cast<__half*>(dsm + 128 * ASH * 2);

    const int t    = threadIdx.x;
    const int w    = t >> 5;
    const int lane = t & 31;
    const int g    = lane >> 2;
    const int tig  = lane & 3;
    const int wm   = (w >> 2) * 32;   // 4 M-groups of 32 rows
    const int wn   = (w & 3) * 32;    // 4 N-groups of 32 cols

    const uint32_t AfA = smem_u32(Af);
    const uint32_t BsA = smem_u32(Bs);

    if (t < D) s_bias[t] = bias1[t];
    load_b_tile(Bs, B1, t);

    const int ntiles = (M + 127) >> 7;
    float acc[2][4][4];

    if (AH16) {
        const __half* A = (const __half*)Ain;
        __syncthreads();
        for (int tile = blockIdx.x; tile < ntiles; tile += gridDim.x) {
            load_a_f16(Af, A, tile << 7, M, t);
            __syncthreads();
            #pragma unroll
            for (int i = 0; i < 2; i++)
                #pragma unroll
                for (int j = 0; j < 4; j++)
                    #pragma unroll
                    for (int q = 0; q < 4; q++) acc[i][j][q] = 0.f;
            mma_compute(acc, AfA, BsA, wm, wn, lane);
            epilogue<RELU, ADDC, WH16>(acc, C, Ch, s_bias, tile << 7, M, wm, wn, g, tig);
            __syncthreads();
        }
    } else {
        const float* A = (const float*)Ain;
        float4 buf[8];
        int tile = blockIdx.x;
        if (tile < ntiles) ldg_tile(buf, A, tile << 7, M, t);
        __syncthreads();  // Bs ready
        for (; tile < ntiles; tile += gridDim.x) {
            sts_convert(buf, Af, tile << 7, M, t);
            __syncthreads();  // Af ready
            int nt2 = tile + gridDim.x;
            if (nt2 < ntiles) ldg_tile(buf, A, nt2 << 7, M, t);  // overlaps MMA
            #pragma unroll
            for (int i = 0; i < 2; i++)
                #pragma unroll
                for (int j = 0; j < 4; j++)
                    #pragma unroll
                    for (int q = 0; q < 4; q++) acc[i][j][q] = 0.f;
            mma_compute(acc, AfA, BsA, wm, wn, lane);
            epilogue<RELU, ADDC, WH16>(acc, C, Ch, s_bias, tile << 7, M, wm, wn, g, tig);
            __syncthreads();  // all warps done reading Af
        }
    }
}

// ---------------- launch ----------------
extern "C" void kernel_launch(void* const* d_in, const int* in_sizes, int n_in,
                              void* d_out, int out_size) {
    const float* features = (const float*)d_in[0];
    const int*   src0     = (const int*)d_in[1];
    const int*   dst0     = (const int*)d_in[2];
    const int*   src1     = (const int*)d_in[3];
    const int*   dst1     = (const int*)d_in[4];
    const float* W_init   = (const float*)d_in[5];
    const float* b_init   = (const float*)d_in[6];
    const float* W_self   = (const float*)d_in[7];
    const float* b_self   = (const float*)d_in[8];
    const float* W_neigh  = (const float*)d_in[9];
    const float* b_neigh  = (const float*)d_in[10];
    float*       out      = (float*)d_out;

    float *h1, *agg0, *agg1;
    __half *h0h, *h1h;
    int *off0, *esrc0, *off1, *esrc1;
    cudaGetSymbolAddress((void**)&h1, g_h1);
    cudaGetSymbolAddress((void**)&agg0, g_agg0);
    cudaGetSymbolAddress((void**)&agg1, g_agg1);
    cudaGetSymbolAddress((void**)&h0h, g_h0h);
    cudaGetSymbolAddress((void**)&h1h, g_h1h);
    cudaGetSymbolAddress((void**)&off0, g_off0);
    cudaGetSymbolAddress((void**)&esrc0, g_esrc0);
    cudaGetSymbolAddress((void**)&off1, g_off1);
    cudaGetSymbolAddress((void**)&esrc1, g_esrc1);

    const int SMEM_BYTES = 2 * 128 * ASH * 2;  // 69632 (no fp32 stage)
    static bool s_init = false;
    static cudaStream_t s_side;
    static cudaEvent_t ev_fork, ev_csr, ev_h0, ev_self2, ev_h1, ev_self3;
    if (!s_init) {
        cudaFuncSetAttribute(tc_gemm_kernel<1, 0, 0, 1>, cudaFuncAttributeMaxDynamicSharedMemorySize, SMEM_BYTES);
        cudaFuncSetAttribute(tc_gemm_kernel<0, 0, 1, 0>, cudaFuncAttributeMaxDynamicSharedMemorySize, SMEM_BYTES);
        cudaFuncSetAttribute(tc_gemm_kernel<1, 1, 0, 1>, cudaFuncAttributeMaxDynamicSharedMemorySize, SMEM_BYTES);
        cudaFuncSetAttribute(tc_gemm_kernel<0, 1, 0, 0>, cudaFuncAttributeMaxDynamicSharedMemorySize, SMEM_BYTES);
        cudaStreamCreateWithFlags(&s_side, cudaStreamNonBlocking);
        cudaEventCreateWithFlags(&ev_fork, cudaEventDisableTiming);
        cudaEventCreateWithFlags(&ev_csr, cudaEventDisableTiming);
        cudaEventCreateWithFlags(&ev_h0, cudaEventDisableTiming);
        cudaEventCreateWithFlags(&ev_self2, cudaEventDisableTiming);
        cudaEventCreateWithFlags(&ev_h1, cudaEventDisableTiming);
        cudaEventCreateWithFlags(&ev_self3, cudaEventDisableTiming);
        s_init = true;
    }

    // ---- fork: CSR chain on side stream, GEMM1 on main stream (GEMM1 stays launch #4) ----
    cudaEventRecord(ev_fork, 0);
    cudaStreamWaitEvent(s_side, ev_fork, 0);

    zero_counts_kernel<<<(NDST0 + 255) / 256, 256, 0, s_side>>>();           // #1
    hist_kernel<<<(E0 + 255) / 256, 256, 0, s_side>>>(dst0, dst1);           // #2
    scan_blocks_kernel<<<NB0 + NB1, 1024, 0, s_side>>>();                    // #3

    tc_gemm_kernel<1, 0, 0, 1><<<148, NT, SMEM_BYTES>>>(                     // #4 (profiled)
        features, W_init, b_init, nullptr, h0h, NSRC0);
    cudaEventRecord(ev_h0, 0);

    scan_apply_kernel<<<NB0 + NB1, 1024, 0, s_side>>>();                     // #5
    scatter_kernel<<<(E0 + 255) / 256, 256, 0, s_side>>>(src0, dst0, src1, dst1);  // #6
    cudaEventRecord(ev_csr, s_side);

    cudaStreamWaitEvent(s_side, ev_h0, 0);
    tc_gemm_kernel<0, 0, 1, 0><<<148, NT, SMEM_BYTES, s_side>>>(
        h0h, W_self, b_self, h1, nullptr, NDST0);
    cudaEventRecord(ev_self2, s_side);

    cudaStreamWaitEvent(0, ev_csr, 0);
    aggregate_kernel<<<(NDST0 * 32 + 255) / 256, 256>>>(h0h, off0, esrc0, agg0, NDST0);

    cudaStreamWaitEvent(0, ev_self2, 0);
    tc_gemm_kernel<1, 1, 0, 1><<<148, NT, SMEM_BYTES>>>(
        agg0, W_neigh, b_neigh, h1, h1h, NDST0);
    cudaEventRecord(ev_h1, 0);

    cudaStreamWaitEvent(s_side, ev_h1, 0);
    tc_gemm_kernel<0, 0, 1, 0><<<79, NT, SMEM_BYTES, s_side>>>(
        h1h, W_self, b_self, out, nullptr, NDST1);
    cudaEventRecord(ev_self3, s_side);

    aggregate_kernel<<<(NDST1 * 32 + 255) / 256, 256>>>(h1h, off1, esrc1, agg1, NDST1);

    cudaStreamWaitEvent(0, ev_self3, 0);
    tc_gemm_kernel<0, 1, 0, 0><<<79, NT, SMEM_BYTES>>>(
        agg1, W_neigh, b_neigh, out, nullptr, NDST1);
}